// round 13
// baseline (speedup 1.0000x reference)
#include <cuda_runtime.h>
#include <cuda_bf16.h>
#include <math.h>
#include <stdint.h>

#define N 4096
#define D 512
#define TAU_INV 5.0f
#define KSEL 820          // N - floor(0.8*(N-1)) = 4096 - 3276
#define NB 32             // 128-wide tiles per dim
#define NTILES 528
#define STG2 8            // D / 64
#define NBINS 256
#define NCOPY 8
#define SMEM_GEMM_BYTES 98304   // 3 stages x 32 KB

// ---- device scratch (allocation-free) ----
__device__ __nv_bfloat16 g_hnh[(size_t)N * D];
__device__ float g_S[(size_t)N * N];
__device__ int   g_partner[N];
__device__ int   g_pneg[N];
__device__ int   g_pairidx[N];
__device__ float g_posexp[N];

__device__ __forceinline__ uint32_t smem_u32(const void* p) {
    uint32_t a;
    asm("{ .reg .u64 t; cvta.to.shared.u64 t, %1; cvt.u32.u64 %0, t; }" : "=r"(a) : "l"(p));
    return a;
}

// ---------------------------------------------------------------- fused prep (single block)
__global__ __launch_bounds__(1024) void k_prep(const int* __restrict__ pairs, int P,
                                               float* out) {
    int tid = threadIdx.x;
    if (tid == 0) out[0] = 0.0f;
    for (int i = tid; i < N; i += 1024) { g_partner[i] = -1; g_pairidx[i] = -1; }
    __syncthreads();
    for (int k = tid; k < P; k += 1024) {
        g_partner[pairs[2 * k]] = pairs[2 * k + 1];
        g_pairidx[pairs[2 * k]] = k;
    }
    __syncthreads();
    for (int i = tid; i < N; i += 1024) {
        int j = N - 1;
        while (j >= 0 && (j == i || g_partner[j] == i)) j--;
        g_pneg[i] = (j < 0) ? (N - 1) : j;
    }
}

// ---------------------------------------------------------------- fused hn (blocks 0..511) + pos (blocks 512..)
__global__ __launch_bounds__(256) void k_hnpos(const float* __restrict__ E,
                                               const int* __restrict__ pairs, int P) {
    int lane = threadIdx.x & 31;
    if (blockIdx.x < 512) {
        int w = blockIdx.x * 8 + (threadIdx.x >> 5);
        int pn = g_pneg[w];
        const float4* ei = (const float4*)(E + (size_t)w * D) + lane * 4;
        const float4* ep = (const float4*)(E + (size_t)pn * D) + lane * 4;
        float v[16];
        float ss = 0.0f;
#pragma unroll
        for (int q = 0; q < 4; q++) {
            float4 a = ei[q], b = ep[q];
            float m0 = 0.5f * a.x + 0.5f * b.x;
            float m1 = 0.5f * a.y + 0.5f * b.y;
            float m2 = 0.5f * a.z + 0.5f * b.z;
            float m3 = 0.5f * a.w + 0.5f * b.w;
            v[q * 4 + 0] = m0; v[q * 4 + 1] = m1; v[q * 4 + 2] = m2; v[q * 4 + 3] = m3;
            ss = fmaf(m0, m0, ss); ss = fmaf(m1, m1, ss);
            ss = fmaf(m2, m2, ss); ss = fmaf(m3, m3, ss);
        }
#pragma unroll
        for (int off = 16; off; off >>= 1) ss += __shfl_xor_sync(0xffffffffu, ss, off);
        float inv = 1.0f / fmaxf(sqrtf(ss), 1e-8f);
        __nv_bfloat16 h[16];
#pragma unroll
        for (int q = 0; q < 16; q++) h[q] = __float2bfloat16(v[q] * inv);
        uint4* dst = (uint4*)(g_hnh + (size_t)w * D + lane * 16);
        dst[0] = ((uint4*)h)[0];
        dst[1] = ((uint4*)h)[1];
    } else {
        int k = (blockIdx.x - 512) * 8 + (threadIdx.x >> 5);
        if (k >= P) return;
        int i = pairs[2 * k], j = pairs[2 * k + 1];
        int pi = g_partner[i], pj = g_partner[j];
        const float4* Ei  = (const float4*)(E + (size_t)i * D) + lane * 4;
        const float4* Ej  = (const float4*)(E + (size_t)j * D) + lane * 4;
        const float4* Epi = (const float4*)(E + (size_t)((pi >= 0) ? pi : 0) * D) + lane * 4;
        const float4* Epj = (const float4*)(E + (size_t)((pj >= 0) ? pj : 0) * D) + lane * 4;
        float daa = 0.f, dab = 0.f, dbb = 0.f;
#pragma unroll
        for (int q = 0; q < 4; q++) {
            float4 e1 = Ei[q], e2 = Ej[q], p1 = Epi[q], p2 = Epj[q];
            float a0 = (pi >= 0) ? (1.5f * e1.x - 0.5f * p1.x) : e1.x;
            float a1 = (pi >= 0) ? (1.5f * e1.y - 0.5f * p1.y) : e1.y;
            float a2 = (pi >= 0) ? (1.5f * e1.z - 0.5f * p1.z) : e1.z;
            float a3 = (pi >= 0) ? (1.5f * e1.w - 0.5f * p1.w) : e1.w;
            float b0 = (pj >= 0) ? (1.5f * e2.x - 0.5f * p2.x) : e2.x;
            float b1 = (pj >= 0) ? (1.5f * e2.y - 0.5f * p2.y) : e2.y;
            float b2 = (pj >= 0) ? (1.5f * e2.z - 0.5f * p2.z) : e2.z;
            float b3 = (pj >= 0) ? (1.5f * e2.w - 0.5f * p2.w) : e2.w;
            daa = fmaf(a0, a0, fmaf(a1, a1, fmaf(a2, a2, fmaf(a3, a3, daa))));
            dab = fmaf(a0, b0, fmaf(a1, b1, fmaf(a2, b2, fmaf(a3, b3, dab))));
            dbb = fmaf(b0, b0, fmaf(b1, b1, fmaf(b2, b2, fmaf(b3, b3, dbb))));
        }
#pragma unroll
        for (int off = 16; off; off >>= 1) {
            daa += __shfl_xor_sync(0xffffffffu, daa, off);
            dab += __shfl_xor_sync(0xffffffffu, dab, off);
            dbb += __shfl_xor_sync(0xffffffffu, dbb, off);
        }
        if (lane == 0) {
            float cosv = dab / (fmaxf(sqrtf(daa), 1e-8f) * fmaxf(sqrtf(dbb), 1e-8f));
            g_posexp[k] = expf(cosv * TAU_INV);
        }
    }
}

// ---------------------------------------------------------------- bf16 mma GEMM (3-stage pipeline)
__device__ __forceinline__ void mma16(float* c, const uint32_t* a, const uint32_t* b) {
    asm volatile(
        "mma.sync.aligned.m16n8k16.row.col.f32.bf16.bf16.f32 "
        "{%0,%1,%2,%3}, {%4,%5,%6,%7}, {%8,%9}, {%0,%1,%2,%3};"
        : "+f"(c[0]), "+f"(c[1]), "+f"(c[2]), "+f"(c[3])
        : "r"(a[0]), "r"(a[1]), "r"(a[2]), "r"(a[3]), "r"(b[0]), "r"(b[1]));
}

__device__ __forceinline__ void ldsm_x4(uint32_t* r, uint32_t addr) {
    asm volatile("ldmatrix.sync.aligned.m8n8.x4.shared.b16 {%0,%1,%2,%3}, [%4];"
                 : "=r"(r[0]), "=r"(r[1]), "=r"(r[2]), "=r"(r[3]) : "r"(addr));
}

__device__ __forceinline__ void cp16(uint32_t dst, const void* src) {
    asm volatile("cp.async.cg.shared.global [%0], [%1], 16;" :: "r"(dst), "l"(src));
}

__global__ __launch_bounds__(512, 2) void k_gemm_bf16() {
    extern __shared__ char sm[];
    uint32_t sbase = smem_u32(sm);
    int tid = threadIdx.x;
    int lane = tid & 31, warp = tid >> 5;
    int wm = warp >> 2, wn = warp & 3;   // 4(M) x 4(N) warps, warp tile 32x32
    int g = lane >> 3, r8 = lane & 7;
    int ahi = g >> 1;

    int t = blockIdx.x, by = 0, rem = t;
    while (rem >= (NB - by)) { rem -= (NB - by); ++by; }
    int bx = by + rem;   // bx >= by

    const __nv_bfloat16* Abase = g_hnh + (size_t)by * 128 * D;
    const __nv_bfloat16* Bbase = g_hnh + (size_t)bx * 128 * D;

    float acc[2][4][4];
#pragma unroll
    for (int im = 0; im < 2; im++)
#pragma unroll
        for (int in = 0; in < 4; in++)
#pragma unroll
            for (int r = 0; r < 4; r++) acc[im][in][r] = 0.0f;

    auto async_load = [&](int s, int p) {
        uint32_t dstA = sbase + p * 32768;
        uint32_t dstB = dstA + 16384;
        int k0 = s * 64;
#pragma unroll
        for (int q = 0; q < 2; q++) {
            int id = tid + q * 512;          // 0..1023
            int row = id >> 3, c = id & 7;
            uint32_t off = (uint32_t)(row * 128 + ((c ^ (row & 7)) << 4));
            cp16(dstA + off, Abase + (size_t)row * D + k0 + c * 8);
            cp16(dstB + off, Bbase + (size_t)row * D + k0 + c * 8);
        }
        asm volatile("cp.async.commit_group;" ::: "memory");
    };

    auto compute = [&](int p) {
        uint32_t sA = sbase + p * 32768;
        uint32_t sB = sA + 16384;
        uint32_t arow[2]; int asw[2];
        uint32_t brow[2]; int bsw[2];
#pragma unroll
        for (int im = 0; im < 2; im++) {
            int rowA = wm * 32 + im * 16 + r8 + (g & 1) * 8;
            arow[im] = sA + rowA * 128;
            asw[im] = rowA & 7;
        }
#pragma unroll
        for (int inp = 0; inp < 2; inp++) {
            int rowB = wn * 32 + inp * 16 + r8 + (g >> 1) * 8;
            brow[inp] = sB + rowB * 128;
            bsw[inp] = rowB & 7;
        }
#pragma unroll
        for (int ks = 0; ks < 4; ks++) {
            uint32_t a[2][4], b2[2][4];
#pragma unroll
            for (int im = 0; im < 2; im++)
                ldsm_x4(a[im], arow[im] + (uint32_t)((((ks << 1) | ahi) ^ asw[im]) << 4));
#pragma unroll
            for (int inp = 0; inp < 2; inp++)
                ldsm_x4(b2[inp], brow[inp] + (uint32_t)((((ks << 1) | (g & 1)) ^ bsw[inp]) << 4));
#pragma unroll
            for (int im = 0; im < 2; im++)
#pragma unroll
                for (int in = 0; in < 4; in++)
                    mma16(acc[im][in], a[im], &b2[in >> 1][(in & 1) << 1]);
        }
    };

    // 3-stage pipeline: one barrier per stage, prefetch depth 2
    async_load(0, 0);
    async_load(1, 1);
    for (int s = 0; s < STG2; s++) {
        if (s + 1 < STG2)
            asm volatile("cp.async.wait_group 1;" ::: "memory");
        else
            asm volatile("cp.async.wait_group 0;" ::: "memory");
        __syncthreads();   // stage s ready everywhere; all warps done with buffer (s+2)%3
        if (s + 2 < STG2) async_load(s + 2, (s + 2) % 3);
        compute(s % 3);
    }
    __syncthreads();   // all warps done before smem reuse by epilogue

    // ---- epilogue via 128x132 fp32 smem tile ----
    float* stg = (float*)sm;
#pragma unroll
    for (int im = 0; im < 2; im++) {
        int row = wm * 32 + im * 16 + (lane >> 2);
#pragma unroll
        for (int in = 0; in < 4; in++) {
            int col = wn * 32 + in * 8 + (lane & 3) * 2;
            stg[row * 132 + col]           = acc[im][in][0];
            stg[row * 132 + col + 1]       = acc[im][in][1];
            stg[(row + 8) * 132 + col]     = acc[im][in][2];
            stg[(row + 8) * 132 + col + 1] = acc[im][in][3];
        }
    }
    __syncthreads();

    float* __restrict__ S = g_S;
    int r0 = by * 128, c0 = bx * 128;
#pragma unroll
    for (int q = 0; q < 8; q++) {
        int v = tid + q * 512;
        int row = v >> 5, c4 = (v & 31) << 2;
        float4 x = *(const float4*)(stg + row * 132 + c4);
        *(float4*)(S + (size_t)(r0 + row) * N + c0 + c4) = x;
    }
    if (bx != by) {
#pragma unroll
        for (int q = 0; q < 8; q++) {
            int v = tid + q * 512;
            int col = v >> 5, r4 = (v & 31) << 2;
            float4 x;
            x.x = stg[(r4 + 0) * 132 + col];
            x.y = stg[(r4 + 1) * 132 + col];
            x.z = stg[(r4 + 2) * 132 + col];
            x.w = stg[(r4 + 3) * 132 + col];
            *(float4*)(S + (size_t)(c0 + col) * N + r0 + r4) = x;
        }
    }
}

// ---------------------------------------------------------------- per-row top-K selection + sum + loss
// 8 shared whist copies, transposed layout whist[bin*8 + (w&7)], RED.S updates.
__device__ __forceinline__ int bin_of(float v) {
    int b = (int)((v + 1.0f) * 128.0f);
    return b < 0 ? 0 : (b > (NBINS - 1) ? (NBINS - 1) : b);
}

__global__ __launch_bounds__(512, 4) void k_select(float* __restrict__ out, int P) {
    __shared__ float sval[N];                        // 16 KB
    __shared__ unsigned whist[NBINS * NCOPY];        // 8 KB, [bin*8 + copy]
    __shared__ int   hist[NBINS];                    // 1 KB
    __shared__ float list[2048];                     // 8 KB
    __shared__ int   shist[256];                     // 1 KB
    __shared__ int   s_cnt, s_b, s_kp, s_b2, s_kp2;
    __shared__ float s_thr;
    __shared__ float warpsum[16];

    int row = blockIdx.x;
    int tid = threadIdx.x;
    int lane = tid & 31, w = tid >> 5;
    int pi = g_partner[row];
    const float4* Sr4 = (const float4*)(g_S + (size_t)row * N);

    // front-load both global reads (MLP=2); latency overlaps init+barrier
    float4 va = Sr4[tid];
    float4 vb = Sr4[tid + 512];

    // whist init: 2048 words = 512 uint4 -> exactly one STS.128 per thread
    ((uint4*)whist)[tid] = make_uint4(0u, 0u, 0u, 0u);
    if (tid < 256) shist[tid] = 0;
    if (tid == 0) { s_cnt = 0; s_thr = -3.0f; s_b = 0; s_kp = 1; s_b2 = 0; s_kp2 = 1; }
    __syncthreads();

    // mask (rare-path range check), stash, per-copy atomic histogram
    {
        int jb = tid << 2;
        if ((unsigned)(row - jb) < 4u || (unsigned)(pi - jb) < 4u) {
            if (jb + 0 == row || jb + 0 == pi) va.x = -2.0f;
            if (jb + 1 == row || jb + 1 == pi) va.y = -2.0f;
            if (jb + 2 == row || jb + 2 == pi) va.z = -2.0f;
            if (jb + 3 == row || jb + 3 == pi) va.w = -2.0f;
        }
        int jb2 = (tid + 512) << 2;
        if ((unsigned)(row - jb2) < 4u || (unsigned)(pi - jb2) < 4u) {
            if (jb2 + 0 == row || jb2 + 0 == pi) vb.x = -2.0f;
            if (jb2 + 1 == row || jb2 + 1 == pi) vb.y = -2.0f;
            if (jb2 + 2 == row || jb2 + 2 == pi) vb.z = -2.0f;
            if (jb2 + 3 == row || jb2 + 3 == pi) vb.w = -2.0f;
        }
    }
    ((float4*)sval)[tid] = va;
    ((float4*)sval)[tid + 512] = vb;

    int myc = w & (NCOPY - 1);
    {
        float vv[8] = {va.x, va.y, va.z, va.w, vb.x, vb.y, vb.z, vb.w};
#pragma unroll
        for (int c = 0; c < 8; c++)
            atomicAdd(&whist[bin_of(vv[c]) * NCOPY + myc], 1u);   // RED.S fire-and-forget
    }
    __syncthreads();

    // reduce: 8 contiguous u32 per bin = 2 LDS.128
    if (tid < NBINS) {
        uint4 h0 = ((const uint4*)whist)[tid * 2];
        uint4 h1 = ((const uint4*)whist)[tid * 2 + 1];
        hist[tid] = (int)(h0.x + h0.y + h0.z + h0.w + h1.x + h1.y + h1.z + h1.w);
    }
    __syncthreads();

    // locate bin containing KSEL-th largest (suffix scan, 8 bins/lane)
    if (tid < 32) {
        int c = 0;
#pragma unroll
        for (int q = 0; q < 8; q++) c += hist[tid * 8 + q];
        int suf = c;
#pragma unroll
        for (int off = 1; off < 32; off <<= 1) {
            int o = __shfl_down_sync(0xffffffffu, suf, off);
            if (tid + off < 32) suf += o;
        }
        int above = suf - c;
        if (above < KSEL && KSEL <= suf) {
            int remk = KSEL - above;
            int b = tid * 8;
            for (int q = 7; q >= 0; q--) {
                int h = hist[tid * 8 + q];
                if (remk <= h) { b = tid * 8 + q; break; }
                remk -= h;
            }
            s_b = b;
            s_kp = remk;
        }
    }
    __syncthreads();
    int bsel = s_b, kp = s_kp;
    float lo = (float)bsel * (1.0f / 128.0f) - 1.0f;

    // pass 2 (merged): exp-accumulate bins above boundary (provably >= thr),
    // gather boundary-bin candidates + sub-histogram
    float acc = 0.0f;
#pragma unroll
    for (int q = 0; q < 2; q++) {
        float4 v4 = ((const float4*)sval)[tid + q * 512];
        float vv[4] = {v4.x, v4.y, v4.z, v4.w};
#pragma unroll
        for (int c = 0; c < 4; c++) {
            float v = vv[c];
            int b = bin_of(v);
            if (b > bsel) {
                acc += __expf(v * TAU_INV);
            } else if (b == bsel) {
                int idx = atomicAdd(&s_cnt, 1);
                if (idx < 2048) {
                    list[idx] = v;
                    int sb = (int)((v - lo) * 32768.0f);
                    sb = sb < 0 ? 0 : (sb > 255 ? 255 : sb);
                    atomicAdd(&shist[sb], 1);
                }
            }
        }
    }
    __syncthreads();
    int cn = min(s_cnt, 2048);

    // locate sub-bin (8 sub-bins/lane)
    if (tid < 32) {
        int c = 0;
#pragma unroll
        for (int q = 0; q < 8; q++) c += shist[tid * 8 + q];
        int suf = c;
#pragma unroll
        for (int off = 1; off < 32; off <<= 1) {
            int o = __shfl_down_sync(0xffffffffu, suf, off);
            if (tid + off < 32) suf += o;
        }
        int above = suf - c;
        if (above < kp && kp <= suf) {
            int remk = kp - above;
            int b = tid * 8;
            for (int q = 7; q >= 0; q--) {
                int h = shist[tid * 8 + q];
                if (remk <= h) { b = tid * 8 + q; break; }
                remk -= h;
            }
            s_b2 = b;
            s_kp2 = remk;
        }
    }
    __syncthreads();
    int sb2 = s_b2, kp2 = s_kp2;

    // exact tie-aware rank within the chosen sub-bin
    for (int t2 = tid; t2 < cn; t2 += 512) {
        float v = list[t2];
        int vs = (int)((v - lo) * 32768.0f);
        vs = vs < 0 ? 0 : (vs > 255 ? 255 : vs);
        if (vs != sb2) continue;
        int gt = 0, eq = 0;
        for (int m = 0; m < cn; m++) {
            float wv = list[m];
            int ws = (int)((wv - lo) * 32768.0f);
            ws = ws < 0 ? 0 : (ws > 255 ? 255 : ws);
            if (ws == sb2) { gt += (wv > v); eq += (wv == v); }
        }
        if (gt < kp2 && kp2 <= gt + eq) s_thr = v;
    }
    __syncthreads();
    float thr = s_thr;

    // boundary-bin survivors from list (bins > bsel already accumulated)
    for (int t2 = tid; t2 < cn; t2 += 512) {
        float v = list[t2];
        if (v >= thr) acc += __expf(v * TAU_INV);
    }
    for (int off = 16; off; off >>= 1) acc += __shfl_down_sync(0xffffffffu, acc, off);
    if (lane == 0) warpsum[w] = acc;
    __syncthreads();
    if (tid < 16) {
        float x = warpsum[tid];
        for (int off = 8; off; off >>= 1) x += __shfl_down_sync(0x0000ffffu, x, off);
        if (tid == 0) {
            int k = g_pairidx[row];
            if (k >= 0) {
                float pz = g_posexp[k];
                float loss = -logf(pz / (pz + x));
                atomicAdd(out, loss * (1.0f / (float)P));
            }
        }
    }
}

// ---------------------------------------------------------------- launch
extern "C" void kernel_launch(void* const* d_in, const int* in_sizes, int n_in,
                              void* d_out, int out_size) {
    const float* E = (const float*)d_in[0];
    const int* pairs = (const int*)d_in[1];
    float* out = (float*)d_out;
    int P = in_sizes[1] / 2;

    static int smem_set = 0;
    if (!smem_set) {
        cudaFuncSetAttribute(k_gemm_bf16, cudaFuncAttributeMaxDynamicSharedMemorySize,
                             SMEM_GEMM_BYTES);
        smem_set = 1;
    }

    // 4 launches; select is the 4th (ncu capture slot)
    k_prep<<<1, 1024>>>(pairs, P, out);
    k_hnpos<<<512 + (P + 7) / 8, 256>>>(E, pairs, P);
    k_gemm_bf16<<<NTILES, 512, SMEM_GEMM_BYTES>>>();
    k_select<<<N, 512>>>(out, P);
}

// round 14
// speedup vs baseline: 1.4991x; 1.4991x over previous
#include <cuda_runtime.h>
#include <cuda_bf16.h>
#include <math.h>
#include <stdint.h>

#define N 4096
#define D 512
#define TAU_INV 5.0f
#define KSEL 820          // N - floor(0.8*(N-1)) = 4096 - 3276
#define NB 32             // 128-wide tiles per dim
#define NTILES 528
#define STG2 8            // D / 64
#define NBINS 256
#define SMEM_GEMM_BYTES 69632

// ---- device scratch (allocation-free) ----
__device__ __nv_bfloat16 g_hnh[(size_t)N * D];
__device__ float g_S[(size_t)N * N];
__device__ int   g_partner[N];
__device__ int   g_pneg[N];
__device__ int   g_pairidx[N];
__device__ float g_posexp[N];

__device__ __forceinline__ uint32_t smem_u32(const void* p) {
    uint32_t a;
    asm("{ .reg .u64 t; cvta.to.shared.u64 t, %1; cvt.u32.u64 %0, t; }" : "=r"(a) : "l"(p));
    return a;
}

// ---------------------------------------------------------------- fused prep (single block)
__global__ __launch_bounds__(1024) void k_prep(const int* __restrict__ pairs, int P,
                                               float* out) {
    int tid = threadIdx.x;
    if (tid == 0) out[0] = 0.0f;
    for (int i = tid; i < N; i += 1024) { g_partner[i] = -1; g_pairidx[i] = -1; }
    __syncthreads();
    for (int k = tid; k < P; k += 1024) {
        g_partner[pairs[2 * k]] = pairs[2 * k + 1];
        g_pairidx[pairs[2 * k]] = k;
    }
    __syncthreads();
    for (int i = tid; i < N; i += 1024) {
        int j = N - 1;
        while (j >= 0 && (j == i || g_partner[j] == i)) j--;
        g_pneg[i] = (j < 0) ? (N - 1) : j;
    }
}

// ---------------------------------------------------------------- fused hn (blocks 0..511) + pos (blocks 512..)
__global__ __launch_bounds__(256) void k_hnpos(const float* __restrict__ E,
                                               const int* __restrict__ pairs, int P) {
    int lane = threadIdx.x & 31;
    if (blockIdx.x < 512) {
        int w = blockIdx.x * 8 + (threadIdx.x >> 5);
        int pn = g_pneg[w];
        const float4* ei = (const float4*)(E + (size_t)w * D) + lane * 4;
        const float4* ep = (const float4*)(E + (size_t)pn * D) + lane * 4;
        float v[16];
        float ss = 0.0f;
#pragma unroll
        for (int q = 0; q < 4; q++) {
            float4 a = ei[q], b = ep[q];
            float m0 = 0.5f * a.x + 0.5f * b.x;
            float m1 = 0.5f * a.y + 0.5f * b.y;
            float m2 = 0.5f * a.z + 0.5f * b.z;
            float m3 = 0.5f * a.w + 0.5f * b.w;
            v[q * 4 + 0] = m0; v[q * 4 + 1] = m1; v[q * 4 + 2] = m2; v[q * 4 + 3] = m3;
            ss = fmaf(m0, m0, ss); ss = fmaf(m1, m1, ss);
            ss = fmaf(m2, m2, ss); ss = fmaf(m3, m3, ss);
        }
#pragma unroll
        for (int off = 16; off; off >>= 1) ss += __shfl_xor_sync(0xffffffffu, ss, off);
        float inv = 1.0f / fmaxf(sqrtf(ss), 1e-8f);
        __nv_bfloat16 h[16];
#pragma unroll
        for (int q = 0; q < 16; q++) h[q] = __float2bfloat16(v[q] * inv);
        uint4* dst = (uint4*)(g_hnh + (size_t)w * D + lane * 16);
        dst[0] = ((uint4*)h)[0];
        dst[1] = ((uint4*)h)[1];
    } else {
        int k = (blockIdx.x - 512) * 8 + (threadIdx.x >> 5);
        if (k >= P) return;
        int i = pairs[2 * k], j = pairs[2 * k + 1];
        int pi = g_partner[i], pj = g_partner[j];
        const float4* Ei  = (const float4*)(E + (size_t)i * D) + lane * 4;
        const float4* Ej  = (const float4*)(E + (size_t)j * D) + lane * 4;
        const float4* Epi = (const float4*)(E + (size_t)((pi >= 0) ? pi : 0) * D) + lane * 4;
        const float4* Epj = (const float4*)(E + (size_t)((pj >= 0) ? pj : 0) * D) + lane * 4;
        float daa = 0.f, dab = 0.f, dbb = 0.f;
#pragma unroll
        for (int q = 0; q < 4; q++) {
            float4 e1 = Ei[q], e2 = Ej[q], p1 = Epi[q], p2 = Epj[q];
            float a0 = (pi >= 0) ? (1.5f * e1.x - 0.5f * p1.x) : e1.x;
            float a1 = (pi >= 0) ? (1.5f * e1.y - 0.5f * p1.y) : e1.y;
            float a2 = (pi >= 0) ? (1.5f * e1.z - 0.5f * p1.z) : e1.z;
            float a3 = (pi >= 0) ? (1.5f * e1.w - 0.5f * p1.w) : e1.w;
            float b0 = (pj >= 0) ? (1.5f * e2.x - 0.5f * p2.x) : e2.x;
            float b1 = (pj >= 0) ? (1.5f * e2.y - 0.5f * p2.y) : e2.y;
            float b2 = (pj >= 0) ? (1.5f * e2.z - 0.5f * p2.z) : e2.z;
            float b3 = (pj >= 0) ? (1.5f * e2.w - 0.5f * p2.w) : e2.w;
            daa = fmaf(a0, a0, fmaf(a1, a1, fmaf(a2, a2, fmaf(a3, a3, daa))));
            dab = fmaf(a0, b0, fmaf(a1, b1, fmaf(a2, b2, fmaf(a3, b3, dab))));
            dbb = fmaf(b0, b0, fmaf(b1, b1, fmaf(b2, b2, fmaf(b3, b3, dbb))));
        }
#pragma unroll
        for (int off = 16; off; off >>= 1) {
            daa += __shfl_xor_sync(0xffffffffu, daa, off);
            dab += __shfl_xor_sync(0xffffffffu, dab, off);
            dbb += __shfl_xor_sync(0xffffffffu, dbb, off);
        }
        if (lane == 0) {
            float cosv = dab / (fmaxf(sqrtf(daa), 1e-8f) * fmaxf(sqrtf(dbb), 1e-8f));
            g_posexp[k] = expf(cosv * TAU_INV);
        }
    }
}

// ---------------------------------------------------------------- bf16 mma GEMM (R12 2-stage, known good)
__device__ __forceinline__ void mma16(float* c, const uint32_t* a, const uint32_t* b) {
    asm volatile(
        "mma.sync.aligned.m16n8k16.row.col.f32.bf16.bf16.f32 "
        "{%0,%1,%2,%3}, {%4,%5,%6,%7}, {%8,%9}, {%0,%1,%2,%3};"
        : "+f"(c[0]), "+f"(c[1]), "+f"(c[2]), "+f"(c[3])
        : "r"(a[0]), "r"(a[1]), "r"(a[2]), "r"(a[3]), "r"(b[0]), "r"(b[1]));
}

__device__ __forceinline__ void ldsm_x4(uint32_t* r, uint32_t addr) {
    asm volatile("ldmatrix.sync.aligned.m8n8.x4.shared.b16 {%0,%1,%2,%3}, [%4];"
                 : "=r"(r[0]), "=r"(r[1]), "=r"(r[2]), "=r"(r[3]) : "r"(addr));
}

__device__ __forceinline__ void cp16(uint32_t dst, const void* src) {
    asm volatile("cp.async.cg.shared.global [%0], [%1], 16;" :: "r"(dst), "l"(src));
}

__global__ __launch_bounds__(512, 2) void k_gemm_bf16() {
    extern __shared__ char sm[];
    uint32_t sbase = smem_u32(sm);
    int tid = threadIdx.x;
    int lane = tid & 31, warp = tid >> 5;
    int wm = warp >> 2, wn = warp & 3;   // 4(M) x 4(N) warps, warp tile 32x32
    int g = lane >> 3, r8 = lane & 7;
    int ahi = g >> 1;

    int t = blockIdx.x, by = 0, rem = t;
    while (rem >= (NB - by)) { rem -= (NB - by); ++by; }
    int bx = by + rem;   // bx >= by

    const __nv_bfloat16* Abase = g_hnh + (size_t)by * 128 * D;
    const __nv_bfloat16* Bbase = g_hnh + (size_t)bx * 128 * D;

    float acc[2][4][4];
#pragma unroll
    for (int im = 0; im < 2; im++)
#pragma unroll
        for (int in = 0; in < 4; in++)
#pragma unroll
            for (int r = 0; r < 4; r++) acc[im][in][r] = 0.0f;

    auto async_load = [&](int s, int p) {
        uint32_t dstA = sbase + p * 32768;
        uint32_t dstB = dstA + 16384;
        int k0 = s * 64;
#pragma unroll
        for (int q = 0; q < 2; q++) {
            int id = tid + q * 512;          // 0..1023
            int row = id >> 3, c = id & 7;
            uint32_t off = (uint32_t)(row * 128 + ((c ^ (row & 7)) << 4));
            cp16(dstA + off, Abase + (size_t)row * D + k0 + c * 8);
            cp16(dstB + off, Bbase + (size_t)row * D + k0 + c * 8);
        }
        asm volatile("cp.async.commit_group;" ::: "memory");
    };

    auto compute = [&](int p) {
        uint32_t sA = sbase + p * 32768;
        uint32_t sB = sA + 16384;
        uint32_t arow[2]; int asw[2];
        uint32_t brow[2]; int bsw[2];
#pragma unroll
        for (int im = 0; im < 2; im++) {
            int rowA = wm * 32 + im * 16 + r8 + (g & 1) * 8;
            arow[im] = sA + rowA * 128;
            asw[im] = rowA & 7;
        }
#pragma unroll
        for (int inp = 0; inp < 2; inp++) {
            int rowB = wn * 32 + inp * 16 + r8 + (g >> 1) * 8;
            brow[inp] = sB + rowB * 128;
            bsw[inp] = rowB & 7;
        }
#pragma unroll
        for (int ks = 0; ks < 4; ks++) {
            uint32_t a[2][4], b2[2][4];
#pragma unroll
            for (int im = 0; im < 2; im++)
                ldsm_x4(a[im], arow[im] + (uint32_t)((((ks << 1) | ahi) ^ asw[im]) << 4));
#pragma unroll
            for (int inp = 0; inp < 2; inp++)
                ldsm_x4(b2[inp], brow[inp] + (uint32_t)((((ks << 1) | (g & 1)) ^ bsw[inp]) << 4));
#pragma unroll
            for (int im = 0; im < 2; im++)
#pragma unroll
                for (int in = 0; in < 4; in++)
                    mma16(acc[im][in], a[im], &b2[in >> 1][(in & 1) << 1]);
        }
    };

    async_load(0, 0);
    for (int s = 0; s < STG2; s++) {
        if (s + 1 < STG2) {
            async_load(s + 1, (s + 1) & 1);
            asm volatile("cp.async.wait_group 1;" ::: "memory");
        } else {
            asm volatile("cp.async.wait_group 0;" ::: "memory");
        }
        __syncthreads();
        compute(s & 1);
        __syncthreads();
    }

    // ---- epilogue via 128x132 fp32 smem tile ----
    float* stg = (float*)sm;
#pragma unroll
    for (int im = 0; im < 2; im++) {
        int row = wm * 32 + im * 16 + (lane >> 2);
#pragma unroll
        for (int in = 0; in < 4; in++) {
            int col = wn * 32 + in * 8 + (lane & 3) * 2;
            stg[row * 132 + col]           = acc[im][in][0];
            stg[row * 132 + col + 1]       = acc[im][in][1];
            stg[(row + 8) * 132 + col]     = acc[im][in][2];
            stg[(row + 8) * 132 + col + 1] = acc[im][in][3];
        }
    }
    __syncthreads();

    float* __restrict__ S = g_S;
    int r0 = by * 128, c0 = bx * 128;
#pragma unroll
    for (int q = 0; q < 8; q++) {
        int v = tid + q * 512;
        int row = v >> 5, c4 = (v & 31) << 2;
        float4 x = *(const float4*)(stg + row * 132 + c4);
        *(float4*)(S + (size_t)(r0 + row) * N + c0 + c4) = x;
    }
    if (bx != by) {
#pragma unroll
        for (int q = 0; q < 8; q++) {
            int v = tid + q * 512;
            int col = v >> 5, r4 = (v & 31) << 2;
            float4 x;
            x.x = stg[(r4 + 0) * 132 + col];
            x.y = stg[(r4 + 1) * 132 + col];
            x.z = stg[(r4 + 2) * 132 + col];
            x.w = stg[(r4 + 3) * 132 + col];
            *(float4*)(S + (size_t)(c0 + col) * N + r0 + r4) = x;
        }
    }
}

// ---------------------------------------------------------------- per-row top-K selection + sum + loss
__device__ __forceinline__ int bin_of(float v) {
    int b = (int)((v + 1.0f) * 128.0f);
    return b < 0 ? 0 : (b > (NBINS - 1) ? (NBINS - 1) : b);
}

__global__ __launch_bounds__(512, 4) void k_select(float* __restrict__ out, int P) {
    __shared__ float sval[N];                        // 16 KB
    __shared__ unsigned whist[16 * NBINS];           // 16 KB (u32 per-warp hist, R12 layout)
    __shared__ int   hist[NBINS];                    // 1 KB
    __shared__ float list[2048];                     // 8 KB
    __shared__ float list2[256];                     // 1 KB (sub-bin candidates)
    __shared__ int   shist[256];                     // 1 KB
    __shared__ int   s_cnt, s_cnt2, s_b, s_kp, s_b2, s_kp2;
    __shared__ float s_thr;
    __shared__ float warpsum[16];

    int row = blockIdx.x;
    int tid = threadIdx.x;
    int lane = tid & 31, w = tid >> 5;
    int pi = g_partner[row];
    const float4* Sr4 = (const float4*)(g_S + (size_t)row * N);

    // front-load both global reads (MLP=2); latency overlaps init+barrier
    float4 va = Sr4[tid];
    float4 vb = Sr4[tid + 512];

    // whist init: 4096 u32 = 1024 uint4 -> 2 STS.128 per thread
    ((uint4*)whist)[tid] = make_uint4(0u, 0u, 0u, 0u);
    ((uint4*)whist)[tid + 512] = make_uint4(0u, 0u, 0u, 0u);
    if (tid < 256) shist[tid] = 0;
    if (tid == 0) { s_cnt = 0; s_cnt2 = 0; s_thr = -3.0f; s_b = 0; s_kp = 1; s_b2 = 0; s_kp2 = 1; }
    __syncthreads();

    // mask (rare-path range check), stash, per-warp atomic histogram
    {
        int jb = tid << 2;
        if ((unsigned)(row - jb) < 4u || (unsigned)(pi - jb) < 4u) {
            if (jb + 0 == row || jb + 0 == pi) va.x = -2.0f;
            if (jb + 1 == row || jb + 1 == pi) va.y = -2.0f;
            if (jb + 2 == row || jb + 2 == pi) va.z = -2.0f;
            if (jb + 3 == row || jb + 3 == pi) va.w = -2.0f;
        }
        int jb2 = (tid + 512) << 2;
        if ((unsigned)(row - jb2) < 4u || (unsigned)(pi - jb2) < 4u) {
            if (jb2 + 0 == row || jb2 + 0 == pi) vb.x = -2.0f;
            if (jb2 + 1 == row || jb2 + 1 == pi) vb.y = -2.0f;
            if (jb2 + 2 == row || jb2 + 2 == pi) vb.z = -2.0f;
            if (jb2 + 3 == row || jb2 + 3 == pi) vb.w = -2.0f;
        }
    }
    ((float4*)sval)[tid] = va;
    ((float4*)sval)[tid + 512] = vb;

    unsigned* wh = whist + w * NBINS;
    {
        float vv[8] = {va.x, va.y, va.z, va.w, vb.x, vb.y, vb.z, vb.w};
#pragma unroll
        for (int c = 0; c < 8; c++)
            atomicAdd(&wh[bin_of(vv[c])], 1u);   // RED.S fire-and-forget
    }
    __syncthreads();

    // reduce per-warp histograms
    if (tid < NBINS) {
        unsigned c = 0;
#pragma unroll
        for (int ww = 0; ww < 16; ww++) c += whist[ww * NBINS + tid];
        hist[tid] = (int)c;
    }
    __syncthreads();

    // locate bin containing KSEL-th largest (suffix scan, 8 bins/lane)
    if (tid < 32) {
        int c = 0;
#pragma unroll
        for (int q = 0; q < 8; q++) c += hist[tid * 8 + q];
        int suf = c;
#pragma unroll
        for (int off = 1; off < 32; off <<= 1) {
            int o = __shfl_down_sync(0xffffffffu, suf, off);
            if (tid + off < 32) suf += o;
        }
        int above = suf - c;
        if (above < KSEL && KSEL <= suf) {
            int remk = KSEL - above;
            int b = tid * 8;
            for (int q = 7; q >= 0; q--) {
                int h = hist[tid * 8 + q];
                if (remk <= h) { b = tid * 8 + q; break; }
                remk -= h;
            }
            s_b = b;
            s_kp = remk;
        }
    }
    __syncthreads();
    int bsel = s_b, kp = s_kp;
    float lo = (float)bsel * (1.0f / 128.0f) - 1.0f;

    // pass 2 (merged): exp-accumulate bins above boundary (provably >= thr),
    // gather boundary-bin candidates + sub-histogram
    float acc = 0.0f;
#pragma unroll
    for (int q = 0; q < 2; q++) {
        float4 v4 = ((const float4*)sval)[tid + q * 512];
        float vv[4] = {v4.x, v4.y, v4.z, v4.w};
#pragma unroll
        for (int c = 0; c < 4; c++) {
            float v = vv[c];
            int b = bin_of(v);
            if (b > bsel) {
                acc += __expf(v * TAU_INV);
            } else if (b == bsel) {
                int idx = atomicAdd(&s_cnt, 1);
                if (idx < 2048) {
                    list[idx] = v;
                    int sb = (int)((v - lo) * 32768.0f);
                    sb = sb < 0 ? 0 : (sb > 255 ? 255 : sb);
                    atomicAdd(&shist[sb], 1);
                }
            }
        }
    }
    __syncthreads();
    int cn = min(s_cnt, 2048);

    // locate sub-bin (8 sub-bins/lane)
    if (tid < 32) {
        int c = 0;
#pragma unroll
        for (int q = 0; q < 8; q++) c += shist[tid * 8 + q];
        int suf = c;
#pragma unroll
        for (int off = 1; off < 32; off <<= 1) {
            int o = __shfl_down_sync(0xffffffffu, suf, off);
            if (tid + off < 32) suf += o;
        }
        int above = suf - c;
        if (above < kp && kp <= suf) {
            int remk = kp - above;
            int b = tid * 8;
            for (int q = 7; q >= 0; q--) {
                int h = shist[tid * 8 + q];
                if (remk <= h) { b = tid * 8 + q; break; }
                remk -= h;
            }
            s_b2 = b;
            s_kp2 = remk;
        }
    }
    __syncthreads();
    int sb2 = s_b2, kp2 = s_kp2;

    // gather sub-bin candidates into tiny list2 (parallel, 1 stripe iter/thread)
    for (int t2 = tid; t2 < cn; t2 += 512) {
        float v = list[t2];
        int vs = (int)((v - lo) * 32768.0f);
        vs = vs < 0 ? 0 : (vs > 255 ? 255 : vs);
        if (vs == sb2) {
            int idx = atomicAdd(&s_cnt2, 1);
            if (idx < 256) list2[idx] = v;
        }
    }
    __syncthreads();
    int cn2 = min(s_cnt2, 256);

    // exact tie-aware rank within the tiny list (parallel, ~cn2^2 total ops, cn2 ~ 1-10)
    if (tid < cn2) {
        float v = list2[tid];
        int gt = 0, eq = 0;
        for (int m = 0; m < cn2; m++) {
            float wv = list2[m];
            gt += (wv > v);
            eq += (wv == v);
        }
        if (gt < kp2 && kp2 <= gt + eq) s_thr = v;
    }
    __syncthreads();
    float thr = s_thr;

    // boundary-bin survivors from list (bins > bsel already accumulated)
    for (int t2 = tid; t2 < cn; t2 += 512) {
        float v = list[t2];
        if (v >= thr) acc += __expf(v * TAU_INV);
    }
    for (int off = 16; off; off >>= 1) acc += __shfl_down_sync(0xffffffffu, acc, off);
    if (lane == 0) warpsum[w] = acc;
    __syncthreads();
    if (tid < 16) {
        float x = warpsum[tid];
        for (int off = 8; off; off >>= 1) x += __shfl_down_sync(0x0000ffffu, x, off);
        if (tid == 0) {
            int k = g_pairidx[row];
            if (k >= 0) {
                float pz = g_posexp[k];
                float loss = -logf(pz / (pz + x));
                atomicAdd(out, loss * (1.0f / (float)P));
            }
        }
    }
}

// ---------------------------------------------------------------- launch
extern "C" void kernel_launch(void* const* d_in, const int* in_sizes, int n_in,
                              void* d_out, int out_size) {
    const float* E = (const float*)d_in[0];
    const int* pairs = (const int*)d_in[1];
    float* out = (float*)d_out;
    int P = in_sizes[1] / 2;

    static int smem_set = 0;
    if (!smem_set) {
        cudaFuncSetAttribute(k_gemm_bf16, cudaFuncAttributeMaxDynamicSharedMemorySize,
                             SMEM_GEMM_BYTES);
        smem_set = 1;
    }

    // 4 launches; select is the 4th (ncu capture slot)
    k_prep<<<1, 1024>>>(pairs, P, out);
    k_hnpos<<<512 + (P + 7) / 8, 256>>>(E, pairs, P);
    k_gemm_bf16<<<NTILES, 512, SMEM_GEMM_BYTES>>>();
    k_select<<<N, 512>>>(out, P);
}